// round 1
// baseline (speedup 1.0000x reference)
#include <cuda_runtime.h>
#include <cstdint>
#include <cstddef>

// Problem constants
#define BB   4096
#define NN   25
#define DD   256
#define HH   8
#define DKK  32
#define DQQ  64
#define MM   (BB*NN)          // 102400

// ---------------- scratch (device globals; no runtime allocation) ----------------
__device__ float g_Bconv[768*768];          // packed conv weights [k=(t,i)][col=(c,o)] (tf32-rounded)
__device__ float g_biasc[HH*NN*NN];         // rel bias + alpha*global bias, [h][n][m]
__device__ float g_C  [(size_t)MM*768];     // conv GEMM output (q|k|v pre-LN)
__device__ float g_q  [(size_t)MM*DD];
__device__ float g_k  [(size_t)MM*DD];
__device__ float g_v  [(size_t)MM*DD];
__device__ float g_qf [(size_t)MM*DQQ];
__device__ float g_ctx[(size_t)MM*DD];

// ---------------- helpers ----------------
__device__ __forceinline__ float to_tf32(float x) {
    unsigned u = __float_as_uint(x);
    asm("cvt.rna.tf32.f32 %0, %0;" : "+r"(u));
    return __uint_as_float(u);
}

__device__ __forceinline__ float tanh_ap(float x) {
    float y; asm("tanh.approx.f32 %0, %1;" : "=f"(y) : "f"(x)); return y;
}

// ---------------- prep: pack conv weights + combined bias ----------------
__global__ void prep_kernel(const float* __restrict__ wq, const float* __restrict__ wk,
                            const float* __restrict__ wv, const float* __restrict__ rel,
                            const float* __restrict__ gb, const float* __restrict__ alpha)
{
    int id = blockIdx.x * blockDim.x + threadIdx.x;
    if (id < 768*768) {
        int kk  = id / 768, col = id % 768;
        int t   = kk >> 8,  i   = kk & 255;
        int c   = col >> 8, o   = col & 255;
        const float* w = (c == 0) ? wq : (c == 1 ? wk : wv);   // [O,I,K] torch layout
        g_Bconv[id] = to_tf32(w[o*768 + i*3 + t]);
    } else {
        int j = id - 768*768;
        if (j < HH*NN*NN) {
            int h = j / (NN*NN);
            int r = j % (NN*NN);
            int n = r / NN, m = r % NN;
            g_biasc[j] = rel[(n - m + NN - 1)*HH + h] + gb[j] * alpha[0];
        }
    }
}

// ---------------- tf32 tensor-core GEMM ----------------
// C[M x N] = A[M x K] * B[K x N] (+bias). M = 102400 (multiple of 128),
// N in {64,256,768} (multiple of 64), K in {256,768} (multiple of 32).
// CONV mode: A is gathered on the fly from x as im2col of the 3-tap conv:
//   A[m][k], k = t*256+i  ->  x[(m+t-1)*256 + i], zero at sequence boundaries.
//   Within a BK=32 tile, t = kb>>3 is constant.
template<bool CONV>
__global__ __launch_bounds__(256)
void gemm_tf32(const float* __restrict__ A, const float* __restrict__ B,
               float* __restrict__ C, const float* __restrict__ bias,
               int N, int K)
{
    __shared__ __align__(16) float As[128][36];   // pad 36: conflict-free frag loads
    __shared__ __align__(16) float Bs[32][72];    // pad 72: (8k+n)%32 distinct

    const int tid  = threadIdx.x;
    const int lane = tid & 31, warp = tid >> 5;
    const int wm   = warp >> 1, wn = warp & 1;    // 4x2 warp grid
    const int g    = lane >> 2, t4 = lane & 3;

    const int m0 = blockIdx.x * 128;
    const int n0 = blockIdx.y * 64;

    // A-load mapping: 4 x float4 per thread
    int arow[4], an[4];
    const int ac4 = (tid & 7) * 4;
    #pragma unroll
    for (int r = 0; r < 4; r++) {
        arow[r] = (tid >> 3) + r * 32;
        an[r]   = (m0 + arow[r]) % 25;
    }
    // B-load mapping: 2 x float4 per thread
    const int brow0 = tid >> 4;
    const int bc4   = (tid & 15) * 4;

    float acc[2][4][4];
    #pragma unroll
    for (int a = 0; a < 2; a++)
        #pragma unroll
        for (int b = 0; b < 4; b++)
            #pragma unroll
            for (int c = 0; c < 4; c++) acc[a][b][c] = 0.f;

    const int KB = K >> 5;
    float4 ar[4], br[2];

    auto load_tiles = [&](int kb) {
        if (CONV) {
            int t3 = kb >> 3;                       // tap index, constant per tile
            int ii = ((kb & 7) << 5) + ac4;         // channel index within D
            #pragma unroll
            for (int r = 0; r < 4; r++) {
                bool valid = (t3 == 1) || (t3 == 0 && an[r] > 0) || (t3 == 2 && an[r] < 24);
                if (valid)
                    ar[r] = *(const float4*)(A + (size_t)(m0 + arow[r] + t3 - 1)*256 + ii);
                else
                    ar[r] = make_float4(0.f, 0.f, 0.f, 0.f);
            }
        } else {
            #pragma unroll
            for (int r = 0; r < 4; r++)
                ar[r] = *(const float4*)(A + (size_t)(m0 + arow[r])*K + (kb << 5) + ac4);
        }
        #pragma unroll
        for (int r = 0; r < 2; r++)
            br[r] = *(const float4*)(B + (size_t)((kb << 5) + brow0 + r*16)*N + n0 + bc4);
    };

    load_tiles(0);
    for (int kb = 0; kb < KB; kb++) {
        // stage current tile into smem with tf32 rounding
        #pragma unroll
        for (int r = 0; r < 4; r++) {
            float4 v = ar[r];
            v.x = to_tf32(v.x); v.y = to_tf32(v.y); v.z = to_tf32(v.z); v.w = to_tf32(v.w);
            *(float4*)&As[arow[r]][ac4] = v;
        }
        #pragma unroll
        for (int r = 0; r < 2; r++) {
            float4 v = br[r];
            v.x = to_tf32(v.x); v.y = to_tf32(v.y); v.z = to_tf32(v.z); v.w = to_tf32(v.w);
            *(float4*)&Bs[brow0 + r*16][bc4] = v;
        }
        __syncthreads();
        if (kb + 1 < KB) load_tiles(kb + 1);      // prefetch under compute

        #pragma unroll
        for (int ks = 0; ks < 4; ks++) {
            unsigned a[2][4], bb[4][2];
            #pragma unroll
            for (int mt = 0; mt < 2; mt++) {
                int r0 = wm*32 + mt*16 + g;
                a[mt][0] = __float_as_uint(As[r0    ][ks*8 + t4    ]);
                a[mt][1] = __float_as_uint(As[r0 + 8][ks*8 + t4    ]);
                a[mt][2] = __float_as_uint(As[r0    ][ks*8 + t4 + 4]);
                a[mt][3] = __float_as_uint(As[r0 + 8][ks*8 + t4 + 4]);
            }
            #pragma unroll
            for (int nt = 0; nt < 4; nt++) {
                int cn = wn*32 + nt*8 + g;
                bb[nt][0] = __float_as_uint(Bs[ks*8 + t4    ][cn]);
                bb[nt][1] = __float_as_uint(Bs[ks*8 + t4 + 4][cn]);
            }
            #pragma unroll
            for (int mt = 0; mt < 2; mt++)
                #pragma unroll
                for (int nt = 0; nt < 4; nt++)
                    asm volatile(
                        "mma.sync.aligned.m16n8k8.row.col.f32.tf32.tf32.f32 "
                        "{%0,%1,%2,%3}, {%4,%5,%6,%7}, {%8,%9}, {%0,%1,%2,%3};\n"
                        : "+f"(acc[mt][nt][0]), "+f"(acc[mt][nt][1]),
                          "+f"(acc[mt][nt][2]), "+f"(acc[mt][nt][3])
                        : "r"(a[mt][0]), "r"(a[mt][1]), "r"(a[mt][2]), "r"(a[mt][3]),
                          "r"(bb[nt][0]), "r"(bb[nt][1]));
        }
        __syncthreads();
    }

    // epilogue
    #pragma unroll
    for (int mt = 0; mt < 2; mt++) {
        int row = m0 + wm*32 + mt*16 + g;
        #pragma unroll
        for (int nt = 0; nt < 4; nt++) {
            int col = n0 + wn*32 + nt*8 + t4*2;
            float b0 = 0.f, b1 = 0.f;
            if (bias) { b0 = __ldg(bias + col); b1 = __ldg(bias + col + 1); }
            float2 v0 = make_float2(acc[mt][nt][0] + b0, acc[mt][nt][1] + b1);
            float2 v1 = make_float2(acc[mt][nt][2] + b0, acc[mt][nt][3] + b1);
            *(float2*)(C + (size_t)row      * N + col) = v0;
            *(float2*)(C + (size_t)(row + 8)* N + col) = v1;
        }
    }
}

// ---------------- LayerNorm + residual ----------------
// grid (4096, 3): block b handles one batch row-set, y=c selects q/k/v slice of g_C.
__global__ __launch_bounds__(256)
void ln_kernel(const float* __restrict__ x,
               const float* __restrict__ g0, const float* __restrict__ b0,
               const float* __restrict__ g1, const float* __restrict__ b1,
               const float* __restrict__ g2, const float* __restrict__ b2)
{
    int b = blockIdx.x, c = blockIdx.y;
    const float* gamma = (c == 0) ? g0 : (c == 1 ? g1 : g2);
    const float* beta  = (c == 0) ? b0 : (c == 1 ? b1 : b2);
    float* out = (c == 0) ? g_q : (c == 1 ? g_k : g_v);

    int lane = threadIdx.x & 31, w = threadIdx.x >> 5;
    for (int n = w; n < 25; n += 8) {
        const float* yrow = g_C + (size_t)(b*25 + n)*768 + c*256;
        float v[8]; float s = 0.f, s2 = 0.f;
        #pragma unroll
        for (int j = 0; j < 8; j++) {
            v[j] = yrow[lane + 32*j]; s += v[j]; s2 += v[j]*v[j];
        }
        #pragma unroll
        for (int o = 16; o; o >>= 1) {
            s  += __shfl_xor_sync(0xffffffffu, s,  o);
            s2 += __shfl_xor_sync(0xffffffffu, s2, o);
        }
        float mu  = s * (1.f/256.f);
        float var = s2 * (1.f/256.f) - mu*mu;
        float rs  = rsqrtf(var + 1e-5f);
        const float* xrow = x + (size_t)(b*25 + n)*256;
        float* orow = out + (size_t)(b*25 + n)*256;
        #pragma unroll
        for (int j = 0; j < 8; j++) {
            int o = lane + 32*j;
            orow[o] = xrow[o] + (v[j] - mu)*rs*__ldg(gamma + o) + __ldg(beta + o);
        }
    }
}

// ---------------- fused attention core (one block per b) ----------------
// smem floats: sq 25*257, skv 25*257, sqf 25*65, sc 5000, wqp 512, bqp 8  -> 79,980 B
__global__ __launch_bounds__(256)
void attn_kernel(const float* __restrict__ wqp, const float* __restrict__ bqp)
{
    extern __shared__ float sm[];
    float* sq   = sm;                   // [25][257] padded (bank-conflict-free)
    float* skv  = sq  + 25*257;         // K, later reused for V
    float* sqf  = skv + 25*257;         // [25][65]
    float* sc   = sqf + 25*65;          // [8][25][25]
    float* swqp = sc  + 5000;           // [64][8]
    float* sbqp = swqp + 512;           // [8]

    int b = blockIdx.x, tid = threadIdx.x;
    const float* qg  = g_q  + (size_t)b*6400;
    const float* kg  = g_k  + (size_t)b*6400;
    const float* vg  = g_v  + (size_t)b*6400;
    const float* qfg = g_qf + (size_t)b*1600;

    #pragma unroll
    for (int j = 0; j < 25; j++) {
        int idx = tid + 256*j; int n = idx >> 8, o = idx & 255;
        sq [n*257 + o] = qg[idx];
        skv[n*257 + o] = kg[idx];
    }
    for (int idx = tid; idx < 1600; idx += 256)
        sqf[(idx >> 6)*65 + (idx & 63)] = qfg[idx];
    for (int j = tid; j < 5000; j += 256) sc[j] = g_biasc[j];
    for (int j = tid; j < 512;  j += 256) swqp[j] = wqp[j];
    if (tid < 8) sbqp[tid] = bqp[tid];
    __syncthreads();

    // phase 1: scores += Q.K^T / sqrt(dk)   (one (h,n) row per thread)
    if (tid < 200) {
        int h = tid / 25, n = tid % 25;
        float qreg[32];
        const float* qp = sq + n*257 + h*32;
        #pragma unroll
        for (int d = 0; d < 32; d++) qreg[d] = qp[d];
        float* srow = sc + h*625 + n*25;
        for (int m = 0; m < 25; m++) {
            const float* kp = skv + m*257 + h*32;
            float a = 0.f;
            #pragma unroll
            for (int d = 0; d < 32; d++) a += qreg[d]*kp[d];
            srow[m] += a * 0.17677669529663687f;   // 1/sqrt(32)
        }
    }
    __syncthreads();

    // phase 2: dynamic adjacency bias
    for (int p = tid; p < 625; p += 256) {
        int n = p / 25, m = p % 25;
        const float* fa = sqf + n*65;
        const float* fb = sqf + m*65;
        float ah[8] = {0,0,0,0,0,0,0,0};
        for (int d = 0; d < 64; d++) {
            float tv = tanh_ap(fa[d] - fb[d]);
            const float* wrow = swqp + d*8;
            #pragma unroll
            for (int h = 0; h < 8; h++) ah[h] += tv * wrow[h];
        }
        #pragma unroll
        for (int h = 0; h < 8; h++) sc[h*625 + p] += ah[h] + sbqp[h];
    }
    __syncthreads();

    // load V into skv (K no longer needed), then softmax rows
    #pragma unroll
    for (int j = 0; j < 25; j++) {
        int idx = tid + 256*j; int n = idx >> 8, o = idx & 255;
        skv[n*257 + o] = vg[idx];
    }
    if (tid < 200) {
        float* row = sc + tid*25;    // tid = h*25+n  ->  offset h*625+n*25
        float mx = row[0];
        #pragma unroll
        for (int m = 1; m < 25; m++) mx = fmaxf(mx, row[m]);
        float e[25]; float s = 0.f;
        #pragma unroll
        for (int m = 0; m < 25; m++) { e[m] = expf(row[m] - mx); s += e[m]; }
        float inv = 1.f / s;
        #pragma unroll
        for (int m = 0; m < 25; m++) row[m] = e[m]*inv;
    }
    __syncthreads();

    // phase 4: ctx = attn @ V   (thread = output channel o)
    int o = tid, h = o >> 5;
    float* og = g_ctx + (size_t)b*6400;
    for (int n = 0; n < 25; n++) {
        const float* srow = sc + h*625 + n*25;
        float a = 0.f;
        #pragma unroll
        for (int m = 0; m < 25; m++) a += srow[m] * skv[m*257 + o];
        og[n*256 + o] = a;
    }
}

// ---------------- launch ----------------
extern "C" void kernel_launch(void* const* d_in, const int* in_sizes, int n_in,
                              void* d_out, int out_size)
{
    const float* x    = (const float*)d_in[0];
    const float* wq   = (const float*)d_in[1];
    const float* wk   = (const float*)d_in[2];
    const float* wv   = (const float*)d_in[3];
    const float* lnqg = (const float*)d_in[4];
    const float* lnqb = (const float*)d_in[5];
    const float* lnkg = (const float*)d_in[6];
    const float* lnkb = (const float*)d_in[7];
    const float* lnvg = (const float*)d_in[8];
    const float* lnvb = (const float*)d_in[9];
    const float* rel  = (const float*)d_in[10];
    const float* gb   = (const float*)d_in[11];
    const float* alpha= (const float*)d_in[12];
    const float* wqf  = (const float*)d_in[13];
    const float* bqf  = (const float*)d_in[14];
    const float* wqp  = (const float*)d_in[15];
    const float* bqp  = (const float*)d_in[16];
    const float* wo   = (const float*)d_in[17];
    const float* bo   = (const float*)d_in[18];
    float* out = (float*)d_out;

    float *pBconv, *pC, *pQf, *pCtx;
    cudaGetSymbolAddress((void**)&pBconv, g_Bconv);
    cudaGetSymbolAddress((void**)&pC,     g_C);
    cudaGetSymbolAddress((void**)&pQf,    g_qf);
    cudaGetSymbolAddress((void**)&pCtx,   g_ctx);

    // 1) pack weights + combined bias
    prep_kernel<<<(768*768 + HH*NN*NN + 255)/256, 256>>>(wq, wk, wv, rel, gb, alpha);

    // 2) conv q|k|v as one im2col GEMM: [102400 x 768] x [768 x 768]
    gemm_tf32<true><<<dim3(800, 12), 256>>>(x, pBconv, pC, nullptr, 768, 768);

    // 3) qf = x @ wqf + bqf : [102400 x 256] x [256 x 64]
    gemm_tf32<false><<<dim3(800, 1), 256>>>(x, wqf, pQf, bqf, 64, 256);

    // 4) LayerNorm + residual -> q,k,v
    ln_kernel<<<dim3(BB, 3), 256>>>(x, lnqg, lnqb, lnkg, lnkb, lnvg, lnvb);

    // 5) fused attention (scores + rel/global/dyn bias + softmax + A@V)
    cudaFuncSetAttribute(attn_kernel, cudaFuncAttributeMaxDynamicSharedMemorySize, 81920);
    attn_kernel<<<BB, 256, 79980>>>(wqp, bqp);

    // 6) out = ctx @ wo + bo : [102400 x 256] x [256 x 256]
    gemm_tf32<false><<<dim3(800, 4), 256>>>(pCtx, wo, out, bo, 256, 256);
}

// round 2
// speedup vs baseline: 1.0431x; 1.0431x over previous
#include <cuda_runtime.h>
#include <cstdint>
#include <cstddef>

// Problem constants
#define BB   4096
#define NN   25
#define DD   256
#define HH   8
#define DQQ  64
#define MM   (BB*NN)          // 102400

// ---------------- scratch (device globals; no runtime allocation) ----------------
__device__ float g_Bconv[768*768];          // packed conv weights [k=(t,i)][col=(c,o)] (tf32-rounded)
__device__ float g_biasc[HH*NN*NN];         // rel bias + alpha*global bias + bqp, [h][n][m]
__device__ float g_C  [(size_t)MM*768];     // conv GEMM output (q|k|v pre-LN)
__device__ float g_qf [(size_t)MM*DQQ];
__device__ float g_ctx[(size_t)MM*DD];

// ---------------- helpers ----------------
__device__ __forceinline__ float to_tf32(float x) {
    unsigned u = __float_as_uint(x);
    asm("cvt.rna.tf32.f32 %0, %0;" : "+r"(u));
    return __uint_as_float(u);
}

__device__ __forceinline__ float tanh_ap(float x) {
    float y; asm("tanh.approx.f32 %0, %1;" : "=f"(y) : "f"(x)); return y;
}

// ---------------- prep: pack conv weights + combined bias ----------------
__global__ void prep_kernel(const float* __restrict__ wq, const float* __restrict__ wk,
                            const float* __restrict__ wv, const float* __restrict__ rel,
                            const float* __restrict__ gb, const float* __restrict__ alpha,
                            const float* __restrict__ bqp)
{
    int id = blockIdx.x * blockDim.x + threadIdx.x;
    if (id < 768*768) {
        int kk  = id / 768, col = id % 768;
        int t   = kk >> 8,  i   = kk & 255;
        int c   = col >> 8, o   = col & 255;
        const float* w = (c == 0) ? wq : (c == 1 ? wk : wv);   // [O,I,K] torch layout
        g_Bconv[id] = to_tf32(w[o*768 + i*3 + t]);
    } else {
        int j = id - 768*768;
        if (j < HH*NN*NN) {
            int h = j / (NN*NN);
            int r = j % (NN*NN);
            int n = r / NN, m = r % NN;
            g_biasc[j] = rel[(n - m + NN - 1)*HH + h] + gb[j] * alpha[0] + bqp[h];
        }
    }
}

// ---------------- tf32 tensor-core GEMM, double-buffered smem ----------------
// C[M x N] = A[M x K] * B[K x N] (+bias). M=102400 (mult of 128), BN in {64,128}.
// CONV mode: A gathered on the fly from x as im2col of the 3-tap conv:
//   A[m][k], k = t*256+i -> x[(m+t-1)*256 + i], zero at sequence boundaries;
//   within a BK=32 tile, t = kb>>3 is constant.
template<bool CONV, int BN>
__global__ __launch_bounds__(256)
void gemm_tf32(const float* __restrict__ A, const float* __restrict__ B,
               float* __restrict__ C, const float* __restrict__ bias,
               int N, int K)
{
    constexpr int NT = BN / 16;       // n-subtiles per warp
    constexpr int BP = BN + 8;        // padded Bs row (mod 32 == 8 -> conflict-free frags)
    constexpr int BC4   = BN / 4;     // float4 columns in B tile
    constexpr int BROWS = 1024 / BN;  // B rows loaded per pass by 256 threads
    constexpr int BPASS = 32 / BROWS;

    extern __shared__ float smem[];
    float* As = smem;                 // [2][128][36]
    float* Bs = smem + 2*128*36;      // [2][32][BP]
    #define ASI(bf,r,c) As[(bf)*128*36 + (r)*36 + (c)]
    #define BSI(bf,r,c) Bs[(bf)*32*BP + (r)*BP + (c)]

    const int tid  = threadIdx.x;
    const int lane = tid & 31, warp = tid >> 5;
    const int wm   = warp >> 1, wn = warp & 1;    // 4x2 warp grid
    const int g    = lane >> 2, t4 = lane & 3;

    const int m0 = blockIdx.x * 128;
    const int n0 = blockIdx.y * BN;

    // A-load mapping: 4 x float4 per thread
    int arow[4], an[4];
    const int ac4 = (tid & 7) * 4;
    #pragma unroll
    for (int r = 0; r < 4; r++) {
        arow[r] = (tid >> 3) + r * 32;
        an[r]   = (m0 + arow[r]) % 25;
    }
    // B-load mapping
    const int brow0 = tid / BC4;
    const int bc4   = (tid % BC4) * 4;

    float acc[2][NT][4];
    #pragma unroll
    for (int a = 0; a < 2; a++)
        #pragma unroll
        for (int b = 0; b < NT; b++)
            #pragma unroll
            for (int c = 0; c < 4; c++) acc[a][b][c] = 0.f;

    const int KB = K >> 5;
    float4 ar[4], br[BPASS];

    auto load_tiles = [&](int kb) {
        if (CONV) {
            int t3 = kb >> 3;                       // tap index, constant per tile
            int ii = ((kb & 7) << 5) + ac4;         // channel index within D
            #pragma unroll
            for (int r = 0; r < 4; r++) {
                bool valid = (t3 == 1) || (t3 == 0 && an[r] > 0) || (t3 == 2 && an[r] < 24);
                if (valid)
                    ar[r] = *(const float4*)(A + (size_t)(m0 + arow[r] + t3 - 1)*256 + ii);
                else
                    ar[r] = make_float4(0.f, 0.f, 0.f, 0.f);
            }
        } else {
            #pragma unroll
            for (int r = 0; r < 4; r++)
                ar[r] = *(const float4*)(A + (size_t)(m0 + arow[r])*K + (kb << 5) + ac4);
        }
        #pragma unroll
        for (int r = 0; r < BPASS; r++)
            br[r] = *(const float4*)(B + (size_t)((kb << 5) + brow0 + r*BROWS)*N + n0 + bc4);
    };

    auto store_tiles = [&](int bf) {
        #pragma unroll
        for (int r = 0; r < 4; r++) {
            float4 v = ar[r];
            v.x = to_tf32(v.x); v.y = to_tf32(v.y); v.z = to_tf32(v.z); v.w = to_tf32(v.w);
            *(float4*)&ASI(bf, arow[r], ac4) = v;
        }
        #pragma unroll
        for (int r = 0; r < BPASS; r++) {
            float4 v = br[r];
            v.x = to_tf32(v.x); v.y = to_tf32(v.y); v.z = to_tf32(v.z); v.w = to_tf32(v.w);
            *(float4*)&BSI(bf, brow0 + r*BROWS, bc4) = v;
        }
    };

    load_tiles(0);
    store_tiles(0);
    __syncthreads();

    for (int kb = 0; kb < KB; kb++) {
        const int bf = kb & 1;
        if (kb + 1 < KB) load_tiles(kb + 1);       // global prefetch under compute

        #pragma unroll
        for (int ks = 0; ks < 4; ks++) {
            unsigned a[2][4], bb[NT][2];
            #pragma unroll
            for (int mt = 0; mt < 2; mt++) {
                int r0 = wm*32 + mt*16 + g;
                a[mt][0] = __float_as_uint(ASI(bf, r0    , ks*8 + t4    ));
                a[mt][1] = __float_as_uint(ASI(bf, r0 + 8, ks*8 + t4    ));
                a[mt][2] = __float_as_uint(ASI(bf, r0    , ks*8 + t4 + 4));
                a[mt][3] = __float_as_uint(ASI(bf, r0 + 8, ks*8 + t4 + 4));
            }
            #pragma unroll
            for (int nt = 0; nt < NT; nt++) {
                int cn = wn*(BN/2) + nt*8 + g;
                bb[nt][0] = __float_as_uint(BSI(bf, ks*8 + t4    , cn));
                bb[nt][1] = __float_as_uint(BSI(bf, ks*8 + t4 + 4, cn));
            }
            #pragma unroll
            for (int mt = 0; mt < 2; mt++)
                #pragma unroll
                for (int nt = 0; nt < NT; nt++)
                    asm volatile(
                        "mma.sync.aligned.m16n8k8.row.col.f32.tf32.tf32.f32 "
                        "{%0,%1,%2,%3}, {%4,%5,%6,%7}, {%8,%9}, {%0,%1,%2,%3};\n"
                        : "+f"(acc[mt][nt][0]), "+f"(acc[mt][nt][1]),
                          "+f"(acc[mt][nt][2]), "+f"(acc[mt][nt][3])
                        : "r"(a[mt][0]), "r"(a[mt][1]), "r"(a[mt][2]), "r"(a[mt][3]),
                          "r"(bb[nt][0]), "r"(bb[nt][1]));
        }

        if (kb + 1 < KB) {
            store_tiles(bf ^ 1);
            __syncthreads();
        }
    }

    // epilogue
    #pragma unroll
    for (int mt = 0; mt < 2; mt++) {
        int row = m0 + wm*32 + mt*16 + g;
        #pragma unroll
        for (int nt = 0; nt < NT; nt++) {
            int col = n0 + wn*(BN/2) + nt*8 + t4*2;
            float b0 = 0.f, b1 = 0.f;
            if (bias) { b0 = __ldg(bias + col); b1 = __ldg(bias + col + 1); }
            float2 v0 = make_float2(acc[mt][nt][0] + b0, acc[mt][nt][1] + b1);
            float2 v1 = make_float2(acc[mt][nt][2] + b0, acc[mt][nt][3] + b1);
            *(float2*)(C + (size_t)row      * N + col) = v0;
            *(float2*)(C + (size_t)(row + 8)* N + col) = v1;
        }
    }
    #undef ASI
    #undef BSI
}

// ---------------- fused attention core (one block per b) ----------------
// Does: LN(q/k/v)+residual from g_C and x, scores+rel/global bias, antisymmetric
// dyn bias (tanh), softmax, A@V -> g_ctx.
// smem floats: sq/sk/sv 3*25*257, sqf 25*65, sc 5000, wqp 512 -> 105,648 B
__global__ __launch_bounds__(256)
void attn_kernel(const float* __restrict__ x, const float* __restrict__ wqp,
                 const float* __restrict__ g0, const float* __restrict__ b0,
                 const float* __restrict__ g1, const float* __restrict__ b1,
                 const float* __restrict__ g2, const float* __restrict__ b2)
{
    extern __shared__ float sm[];
    float* sq   = sm;                   // [25][257]
    float* sk   = sq  + 25*257;
    float* sv   = sk  + 25*257;
    float* sqf  = sv  + 25*257;         // [25][65]
    float* sc   = sqf + 25*65;          // [8][25][25]
    float* swqp = sc  + 5000;           // [64][8]

    const int b = blockIdx.x, tid = threadIdx.x;
    const int lane = tid & 31, w = tid >> 5;

    const float* gammas[3] = {g0, g1, g2};
    const float* betas [3] = {b0, b1, b2};
    float* dsts[3] = {sq, sk, sv};

    // ---- LayerNorm + residual (fused; replaces ln_kernel + q/k/v round-trip) ----
    for (int n = w; n < 25; n += 8) {
        const float* xrow = x + (size_t)(b*25 + n)*256;
        float xr[8];
        #pragma unroll
        for (int j = 0; j < 8; j++) xr[j] = xrow[lane + 32*j];
        const float* crow = g_C + (size_t)(b*25 + n)*768;
        #pragma unroll
        for (int c = 0; c < 3; c++) {
            float v[8]; float s = 0.f, s2 = 0.f;
            #pragma unroll
            for (int j = 0; j < 8; j++) {
                v[j] = crow[c*256 + lane + 32*j]; s += v[j]; s2 += v[j]*v[j];
            }
            #pragma unroll
            for (int o = 16; o; o >>= 1) {
                s  += __shfl_xor_sync(0xffffffffu, s,  o);
                s2 += __shfl_xor_sync(0xffffffffu, s2, o);
            }
            float mu  = s * (1.f/256.f);
            float var = s2 * (1.f/256.f) - mu*mu;
            float rs  = rsqrtf(var + 1e-5f);
            const float* gamma = gammas[c];
            const float* beta  = betas[c];
            float* dst = dsts[c] + n*257;
            #pragma unroll
            for (int j = 0; j < 8; j++) {
                int o = lane + 32*j;
                dst[o] = xr[j] + (v[j] - mu)*rs*__ldg(gamma + o) + __ldg(beta + o);
            }
        }
    }

    const float* qfg = g_qf + (size_t)b*1600;
    for (int idx = tid; idx < 1600; idx += 256)
        sqf[(idx >> 6)*65 + (idx & 63)] = qfg[idx];
    for (int j = tid; j < 5000; j += 256) sc[j] = g_biasc[j];
    for (int j = tid; j < 512;  j += 256) swqp[j] = wqp[j];
    __syncthreads();

    // phase 1: scores += Q.K^T / sqrt(dk)   (one (h,n) row per thread)
    if (tid < 200) {
        int h = tid / 25, n = tid % 25;
        float qreg[32];
        const float* qp = sq + n*257 + h*32;
        #pragma unroll
        for (int d = 0; d < 32; d++) qreg[d] = qp[d];
        float* srow = sc + h*625 + n*25;
        for (int m = 0; m < 25; m++) {
            const float* kp = sk + m*257 + h*32;
            float a = 0.f;
            #pragma unroll
            for (int d = 0; d < 32; d++) a += qreg[d]*kp[d];
            srow[m] += a * 0.17677669529663687f;   // 1/sqrt(32)
        }
    }
    __syncthreads();

    // phase 2: dynamic adjacency bias — antisymmetric: tanh(a-b) = -tanh(b-a),
    // so only the 300 pairs n<m are computed (diagonal contribution is 0;
    // bqp folded into g_biasc at prep).
    for (int p = tid; p < 300; p += 256) {
        int n = 0, rem = p;
        while (rem >= 24 - n) { rem -= 24 - n; n++; }
        int m = n + 1 + rem;
        const float* fa = sqf + n*65;
        const float* fb = sqf + m*65;
        float ah[8] = {0,0,0,0,0,0,0,0};
        for (int d = 0; d < 64; d++) {
            float tv = tanh_ap(fa[d] - fb[d]);
            const float* wrow = swqp + d*8;
            #pragma unroll
            for (int h = 0; h < 8; h++) ah[h] += tv * wrow[h];
        }
        #pragma unroll
        for (int h = 0; h < 8; h++) {
            sc[h*625 + n*25 + m] += ah[h];
            sc[h*625 + m*25 + n] -= ah[h];
        }
    }
    __syncthreads();

    // phase 3: softmax rows
    if (tid < 200) {
        float* row = sc + tid*25;    // tid = h*25+n  ->  offset h*625+n*25
        float mx = row[0];
        #pragma unroll
        for (int m = 1; m < 25; m++) mx = fmaxf(mx, row[m]);
        float e[25]; float s = 0.f;
        #pragma unroll
        for (int m = 0; m < 25; m++) { e[m] = expf(row[m] - mx); s += e[m]; }
        float inv = 1.f / s;
        #pragma unroll
        for (int m = 0; m < 25; m++) row[m] = e[m]*inv;
    }
    __syncthreads();

    // phase 4: ctx = attn @ V   (thread = output channel o)
    int o = tid, h = o >> 5;
    float* og = g_ctx + (size_t)b*6400;
    for (int n = 0; n < 25; n++) {
        const float* srow = sc + h*625 + n*25;
        float a = 0.f;
        #pragma unroll
        for (int m = 0; m < 25; m++) a += srow[m] * sv[m*257 + o];
        og[n*256 + o] = a;
    }
}

// ---------------- launch ----------------
extern "C" void kernel_launch(void* const* d_in, const int* in_sizes, int n_in,
                              void* d_out, int out_size)
{
    const float* x    = (const float*)d_in[0];
    const float* wq   = (const float*)d_in[1];
    const float* wk   = (const float*)d_in[2];
    const float* wv   = (const float*)d_in[3];
    const float* lnqg = (const float*)d_in[4];
    const float* lnqb = (const float*)d_in[5];
    const float* lnkg = (const float*)d_in[6];
    const float* lnkb = (const float*)d_in[7];
    const float* lnvg = (const float*)d_in[8];
    const float* lnvb = (const float*)d_in[9];
    const float* rel  = (const float*)d_in[10];
    const float* gb   = (const float*)d_in[11];
    const float* alpha= (const float*)d_in[12];
    const float* wqf  = (const float*)d_in[13];
    const float* bqf  = (const float*)d_in[14];
    const float* wqp  = (const float*)d_in[15];
    const float* bqp  = (const float*)d_in[16];
    const float* wo   = (const float*)d_in[17];
    const float* bo   = (const float*)d_in[18];
    float* out = (float*)d_out;

    float *pBconv, *pC, *pQf, *pCtx;
    cudaGetSymbolAddress((void**)&pBconv, g_Bconv);
    cudaGetSymbolAddress((void**)&pC,     g_C);
    cudaGetSymbolAddress((void**)&pQf,    g_qf);
    cudaGetSymbolAddress((void**)&pCtx,   g_ctx);

    const int SMEM_G128 = (2*128*36 + 2*32*136) * 4;   // 71,680 B
    const int SMEM_G64  = (2*128*36 + 2*32*72)  * 4;   // 55,296 B
    const int SMEM_ATTN = (3*25*257 + 25*65 + 5000 + 512) * 4;  // 105,648 B

    cudaFuncSetAttribute((const void*)gemm_tf32<true,128>,
                         cudaFuncAttributeMaxDynamicSharedMemorySize, SMEM_G128);
    cudaFuncSetAttribute((const void*)gemm_tf32<false,128>,
                         cudaFuncAttributeMaxDynamicSharedMemorySize, SMEM_G128);
    cudaFuncSetAttribute((const void*)gemm_tf32<false,64>,
                         cudaFuncAttributeMaxDynamicSharedMemorySize, SMEM_G64);
    cudaFuncSetAttribute((const void*)attn_kernel,
                         cudaFuncAttributeMaxDynamicSharedMemorySize, SMEM_ATTN);

    // 1) pack weights + combined bias (incl. bqp)
    prep_kernel<<<(768*768 + HH*NN*NN + 255)/256, 256>>>(wq, wk, wv, rel, gb, alpha, bqp);

    // 2) qf = x @ wqf + bqf : [102400 x 256] x [256 x 64]
    gemm_tf32<false,64><<<dim3(800, 1), 256, SMEM_G64>>>(x, wqf, pQf, bqf, 64, 256);

    // 3) conv q|k|v as one im2col GEMM: [102400 x 768] x [768 x 768]
    gemm_tf32<true,128><<<dim3(800, 6), 256, SMEM_G128>>>(x, pBconv, pC, nullptr, 768, 768);

    // 4) fused LN+residual + attention (scores + biases + softmax + A@V)
    attn_kernel<<<BB, 256, SMEM_ATTN>>>(x, wqp, lnqg, lnqb, lnkg, lnkb, lnvg, lnvb);

    // 5) out = ctx @ wo + bo : [102400 x 256] x [256 x 256]
    gemm_tf32<false,128><<<dim3(800, 2), 256, SMEM_G128>>>(pCtx, wo, out, bo, 256, 256);
}